// round 1
// baseline (speedup 1.0000x reference)
#include <cuda_runtime.h>
#include <cuda_bf16.h>

// Problem constants (WordSmoothCriterion: B=4, T=2048, V=32000, NNZ=801)
#define NROWS 8192
#define VDIM  32000
#define NNZ   801
#define TAU   0.8f
#define RARE  1.0f
#define ALPHA 0.7f

// Scratch (device globals — allocation-free)
__device__ float g_smooth[NROWS];
__device__ float g_ml[NROWS];

// ---------------------------------------------------------------------------
// Kernel 1: per-row partials. One CTA per row, 256 threads.
// ---------------------------------------------------------------------------
__global__ __launch_bounds__(256, 8)
void ws_row_kernel(const float* __restrict__ logp,
                   const float* __restrict__ mask,
                   const float* __restrict__ sim_values,
                   const float* __restrict__ idf_values,
                   const int*   __restrict__ target,
                   const int*   __restrict__ sim_cols)
{
    const int n = blockIdx.x;
    const int r = target[n];

    const float* __restrict__ sv = sim_values + (size_t)r * NNZ;
    const float* __restrict__ iv = idf_values + (size_t)r * NNZ;
    const int*   __restrict__ sc = sim_cols   + (size_t)r * NNZ;
    const float* __restrict__ lp = logp       + (size_t)n * VDIM;

    const float inv_tau = 1.0f / TAU;

    float sum_v  = 0.0f;   // sum of vals
    float sum_gv = 0.0f;   // sum of vals * gathered logp

    // 801 elems / 256 threads -> up to 4 iterations; coalesced contiguous loads
    #pragma unroll 4
    for (int j = threadIdx.x; j < NNZ; j += 256) {
        float s = sv[j];
        float d = iv[j];
        int   c = sc[j];
        float g = __ldg(lp + c);                       // scattered 4B gather
        float v = (s - 1.0f - TAU * RARE * d) * inv_tau;
        float val = __expf(__expf(v) * inv_tau);       // exp(exp(v/tau)/tau)
        sum_v  += val;
        sum_gv += val * g;
    }

    // -------- block reduction of (sum_v, sum_gv) --------
    #pragma unroll
    for (int o = 16; o > 0; o >>= 1) {
        sum_v  += __shfl_down_sync(0xffffffffu, sum_v,  o);
        sum_gv += __shfl_down_sync(0xffffffffu, sum_gv, o);
    }
    __shared__ float s_v[8], s_gv[8];
    const int warp = threadIdx.x >> 5;
    const int lane = threadIdx.x & 31;
    if (lane == 0) { s_v[warp] = sum_v; s_gv[warp] = sum_gv; }
    __syncthreads();
    if (warp == 0) {
        float a = (lane < 8) ? s_v[lane]  : 0.0f;
        float b = (lane < 8) ? s_gv[lane] : 0.0f;
        #pragma unroll
        for (int o = 4; o > 0; o >>= 1) {
            a += __shfl_down_sync(0xffffffffu, a, o);
            b += __shfl_down_sync(0xffffffffu, b, o);
        }
        if (lane == 0) {
            g_smooth[n] = b / a;                        // sum(g * sim) for row n
            g_ml[n]     = __ldg(lp + r) * mask[n];      // lp[n, target[n]] * m[n]
        }
    }
}

// ---------------------------------------------------------------------------
// Kernel 2: final reduction over 8192 rows (single CTA, double precision).
// ---------------------------------------------------------------------------
__global__ __launch_bounds__(1024, 1)
void ws_reduce_kernel(const float* __restrict__ mask, float* __restrict__ out)
{
    double s_sm = 0.0, s_ml = 0.0, s_m = 0.0;
    for (int i = threadIdx.x; i < NROWS; i += 1024) {
        s_sm += (double)g_smooth[i];
        s_ml += (double)g_ml[i];
        s_m  += (double)mask[i];
    }
    #pragma unroll
    for (int o = 16; o > 0; o >>= 1) {
        s_sm += __shfl_down_sync(0xffffffffu, s_sm, o);
        s_ml += __shfl_down_sync(0xffffffffu, s_ml, o);
        s_m  += __shfl_down_sync(0xffffffffu, s_m,  o);
    }
    __shared__ double sh[3][32];
    const int warp = threadIdx.x >> 5;
    const int lane = threadIdx.x & 31;
    if (lane == 0) { sh[0][warp] = s_sm; sh[1][warp] = s_ml; sh[2][warp] = s_m; }
    __syncthreads();
    if (warp == 0) {
        s_sm = (lane < 32) ? sh[0][lane] : 0.0;
        s_ml = (lane < 32) ? sh[1][lane] : 0.0;
        s_m  = (lane < 32) ? sh[2][lane] : 0.0;
        #pragma unroll
        for (int o = 16; o > 0; o >>= 1) {
            s_sm += __shfl_down_sync(0xffffffffu, s_sm, o);
            s_ml += __shfl_down_sync(0xffffffffu, s_ml, o);
            s_m  += __shfl_down_sync(0xffffffffu, s_m,  o);
        }
        if (lane == 0) {
            double smooth_loss = -s_sm / s_m;
            double ml_loss     = -s_ml / s_m;
            out[0] = (float)((double)ALPHA * smooth_loss + (1.0 - (double)ALPHA) * ml_loss);
        }
    }
}

// ---------------------------------------------------------------------------
extern "C" void kernel_launch(void* const* d_in, const int* in_sizes, int n_in,
                              void* d_out, int out_size)
{
    const float* logp       = (const float*)d_in[0];
    const float* mask       = (const float*)d_in[1];
    const float* sim_values = (const float*)d_in[2];
    const float* idf_values = (const float*)d_in[3];
    const int*   target     = (const int*)  d_in[4];
    const int*   sim_cols   = (const int*)  d_in[5];
    float*       out        = (float*)d_out;

    ws_row_kernel<<<NROWS, 256>>>(logp, mask, sim_values, idf_values, target, sim_cols);
    ws_reduce_kernel<<<1, 1024>>>(mask, out);
}

// round 2
// speedup vs baseline: 1.0158x; 1.0158x over previous
#include <cuda_runtime.h>
#include <cuda_bf16.h>

// Problem constants (WordSmoothCriterion: B=4, T=2048, V=32000, NNZ=801)
#define NROWS 8192
#define VDIM  32000
#define NNZ   801
#define TAU   0.8f
#define RARE  1.0f
#define ALPHA 0.7f

// Scratch (device globals — allocation-free)
__device__ float g_smooth[NROWS];   // per-row sum(g*sim)
__device__ float g_ml[NROWS];       // per-row lp[target]*mask
__device__ float g_maskv[NROWS];    // per-row mask
__device__ unsigned int g_count = 0;  // completion counter (self-resetting)

// ---------------------------------------------------------------------------
// Fused kernel: per-row partials + last-block final reduction.
// One CTA per row, 256 threads.
// ---------------------------------------------------------------------------
__global__ __launch_bounds__(256, 8)
void ws_fused_kernel(const float* __restrict__ logp,
                     const float* __restrict__ mask,
                     const float* __restrict__ sim_values,
                     const float* __restrict__ idf_values,
                     const int*   __restrict__ target,
                     const int*   __restrict__ sim_cols,
                     float*       __restrict__ out)
{
    const int n = blockIdx.x;
    const int r = target[n];

    const float* __restrict__ sv = sim_values + (size_t)r * NNZ;
    const float* __restrict__ iv = idf_values + (size_t)r * NNZ;
    const int*   __restrict__ sc = sim_cols   + (size_t)r * NNZ;
    const float* __restrict__ lp = logp       + (size_t)n * VDIM;

    const float inv_tau = 1.0f / TAU;

    float sum_v  = 0.0f;   // sum of vals
    float sum_gv = 0.0f;   // sum of vals * gathered logp

    // 801 elems / 256 threads -> up to 4 iterations; coalesced contiguous loads
    #pragma unroll 4
    for (int j = threadIdx.x; j < NNZ; j += 256) {
        float s = sv[j];
        float d = iv[j];
        int   c = sc[j];
        float g = __ldg(lp + c);                       // scattered 4B gather
        float v = (s - 1.0f - TAU * RARE * d) * inv_tau;
        float val = __expf(__expf(v) * inv_tau);       // exp(exp(v/tau)/tau)
        sum_v  += val;
        sum_gv += val * g;
    }

    // -------- block reduction of (sum_v, sum_gv) --------
    #pragma unroll
    for (int o = 16; o > 0; o >>= 1) {
        sum_v  += __shfl_down_sync(0xffffffffu, sum_v,  o);
        sum_gv += __shfl_down_sync(0xffffffffu, sum_gv, o);
    }
    __shared__ float s_v[8], s_gv[8];
    __shared__ bool  s_last;
    const int warp = threadIdx.x >> 5;
    const int lane = threadIdx.x & 31;
    if (lane == 0) { s_v[warp] = sum_v; s_gv[warp] = sum_gv; }
    __syncthreads();
    if (warp == 0) {
        float a = (lane < 8) ? s_v[lane]  : 0.0f;
        float b = (lane < 8) ? s_gv[lane] : 0.0f;
        #pragma unroll
        for (int o = 4; o > 0; o >>= 1) {
            a += __shfl_down_sync(0xffffffffu, a, o);
            b += __shfl_down_sync(0xffffffffu, b, o);
        }
        if (lane == 0) {
            g_smooth[n] = b / a;                        // sum(g * sim) for row n
            g_ml[n]     = __ldg(lp + r) * mask[n];      // lp[n, target[n]] * m[n]
            g_maskv[n]  = mask[n];
            __threadfence();                            // make partials visible
            unsigned int old = atomicAdd(&g_count, 1u);
            s_last = (old == (unsigned int)(gridDim.x - 1));
        }
    }
    __syncthreads();

    // -------- last CTA performs the final (deterministic) reduction --------
    if (s_last) {
        double d_sm = 0.0, d_ml = 0.0, d_m = 0.0;
        // fixed strided order -> deterministic; data is L2-warm
        for (int i = threadIdx.x; i < NROWS; i += 256) {
            d_sm += (double)g_smooth[i];
            d_ml += (double)g_ml[i];
            d_m  += (double)g_maskv[i];
        }
        #pragma unroll
        for (int o = 16; o > 0; o >>= 1) {
            d_sm += __shfl_down_sync(0xffffffffu, d_sm, o);
            d_ml += __shfl_down_sync(0xffffffffu, d_ml, o);
            d_m  += __shfl_down_sync(0xffffffffu, d_m,  o);
        }
        __shared__ double sh[3][8];
        if (lane == 0) { sh[0][warp] = d_sm; sh[1][warp] = d_ml; sh[2][warp] = d_m; }
        __syncthreads();
        if (warp == 0) {
            d_sm = (lane < 8) ? sh[0][lane] : 0.0;
            d_ml = (lane < 8) ? sh[1][lane] : 0.0;
            d_m  = (lane < 8) ? sh[2][lane] : 0.0;
            #pragma unroll
            for (int o = 4; o > 0; o >>= 1) {
                d_sm += __shfl_down_sync(0xffffffffu, d_sm, o);
                d_ml += __shfl_down_sync(0xffffffffu, d_ml, o);
                d_m  += __shfl_down_sync(0xffffffffu, d_m,  o);
            }
            if (lane == 0) {
                double smooth_loss = -d_sm / d_m;
                double ml_loss     = -d_ml / d_m;
                out[0] = (float)((double)ALPHA * smooth_loss
                                 + (1.0 - (double)ALPHA) * ml_loss);
                g_count = 0;   // reset for next graph replay
            }
        }
    }
}

// ---------------------------------------------------------------------------
extern "C" void kernel_launch(void* const* d_in, const int* in_sizes, int n_in,
                              void* d_out, int out_size)
{
    const float* logp       = (const float*)d_in[0];
    const float* mask       = (const float*)d_in[1];
    const float* sim_values = (const float*)d_in[2];
    const float* idf_values = (const float*)d_in[3];
    const int*   target     = (const int*)  d_in[4];
    const int*   sim_cols   = (const int*)  d_in[5];
    float*       out        = (float*)d_out;

    ws_fused_kernel<<<NROWS, 256>>>(logp, mask, sim_values, idf_values,
                                    target, sim_cols, out);
}